// round 14
// baseline (speedup 1.0000x reference)
#include <cuda_runtime.h>
#include <cstdint>

// ---------------------------------------------------------------------------
// EMGNetQuantized fused BinaryNet inference, XLA-matched fp32 numerics.
// R14 = R12/R13 with the register-spill fixed: NO input-window hoist (scalar
// quad-shared loads per step) so the 8oc x 2x task fits the 84-reg cap of
// __launch_bounds__(256,3) without spilling. Quad-lane remap (lane&3 = oc
// quarter), quad shfl-OR sign assembly, plain stores. FMA2 chains
// bit-identical to R6..R11: (ky,kx,ic) ascending, acc from 0, bias after,
// unfused bn decisions. Phases A/C/D/E unchanged.
// ---------------------------------------------------------------------------

__device__ __align__(16) uint32_t g_w2bits[32 * 9];       // [oc][ky*3+kx], bit=ic
__device__ __align__(16) uint32_t g_wfcbits[516 * 36];    // [o][word], bit=col%32
__device__ __align__(16) float    g_w0p[2304];            // [k=(ky3+kx)*8+ic][oc]
__device__ float g_inv1[32], g_sh1[32];                   // bn1 scale/shift
__device__ float g_inv2[32], g_sh2[32];                   // bn2 scale/shift
__device__ float g_sc3[516], g_sh3[516];                  // bn3 scale/shift

__global__ void prep_kernel(const float* __restrict__ w0,
                            const float* __restrict__ w2,
                            const float* __restrict__ wfc,
                            const float* __restrict__ g1, const float* __restrict__ be1,
                            const float* __restrict__ m1, const float* __restrict__ v1,
                            const float* __restrict__ g2, const float* __restrict__ be2,
                            const float* __restrict__ m2, const float* __restrict__ v2,
                            const float* __restrict__ g3, const float* __restrict__ be3,
                            const float* __restrict__ m3, const float* __restrict__ v3) {
    int t = blockIdx.x * blockDim.x + threadIdx.x;
    if (t < 288) {
        int oc = t / 9, k = t % 9;
        uint32_t w = 0u;
        #pragma unroll 4
        for (int ic = 0; ic < 32; ic++)
            if (w2[oc * 288 + ic * 9 + k] >= 0.f) w |= (1u << ic);
        g_w2bits[t] = w;
    } else if (t < 288 + 18576) {
        int j = t - 288;
        int o = j / 36, c = j % 36;
        const float* row = wfc + o * 1152 + c * 32;
        uint32_t w = 0u;
        #pragma unroll 4
        for (int b = 0; b < 32; b++)
            if (row[b] >= 0.f) w |= (1u << b);
        g_wfcbits[j] = w;
    } else if (t < 288 + 18576 + 32) {
        int c = t - (288 + 18576);
        float inv = __fdiv_rn(g1[c], __fsqrt_rn(__fadd_rn(v1[c], 1e-5f)));
        g_inv1[c] = inv;
        g_sh1[c]  = __fsub_rn(be1[c], __fmul_rn(m1[c], inv));
    } else if (t < 288 + 18576 + 64) {
        int c = t - (288 + 18576 + 32);
        float inv = __fdiv_rn(g2[c], __fsqrt_rn(__fadd_rn(v2[c], 1e-5f)));
        g_inv2[c] = inv;
        g_sh2[c]  = __fsub_rn(be2[c], __fmul_rn(m2[c], inv));
    } else if (t < 288 + 18576 + 64 + 516) {
        int c = t - (288 + 18576 + 64);
        float inv = __fdiv_rn(g3[c], __fsqrt_rn(__fadd_rn(v3[c], 1e-5f)));
        g_sc3[c] = inv;
        g_sh3[c] = __fsub_rn(be3[c], __fmul_rn(m3[c], inv));
    } else if (t < 288 + 18576 + 64 + 516 + 2304) {
        // transpose w0 -> [k][oc] so per-CTA loads are linear/coalesced
        int j  = t - (288 + 18576 + 64 + 516);
        int oc = j & 31;
        int r  = j >> 5;
        int ic = r & 7;
        int kk = r >> 3;                  // ky*3+kx
        g_w0p[j] = w0[oc * 72 + ic * 9 + kk];
    }
}

// ---- f32x2 helpers (per-lane IEEE RN fma; bit-identical to scalar) ---------
__device__ __forceinline__ unsigned long long fma2(unsigned long long a,
                                                   unsigned long long b,
                                                   unsigned long long c) {
    unsigned long long d;
    asm("fma.rn.f32x2 %0, %1, %2, %3;" : "=l"(d) : "l"(a), "l"(b), "l"(c));
    return d;
}
__device__ __forceinline__ unsigned long long pack2(float lo, float hi) {
    unsigned long long r;
    asm("mov.b64 %0, {%1, %2};" : "=l"(r) : "f"(lo), "f"(hi));
    return r;
}
__device__ __forceinline__ float2 unpack2(unsigned long long v) {
    float lo, hi;
    asm("mov.b64 {%0, %1}, %2;" : "=f"(lo), "=f"(hi) : "l"(v));
    return make_float2(lo, hi);
}

#define XPITCH 20   // sx row pitch in floats: 80B rows -> 16B-aligned

// One conv0 task: t = q + 4*(xg + 7*y). The quad (lanes sharing t>>2) covers
// all 32 ocs of outputs (y, 2*xg) and (y, 2*xg+1). No hoisted window: inputs
// are 2 scalar quad-shared LDS.32 per (ky,kx,ic) step -> low register demand.
__device__ __forceinline__ void conv0_task(
        int t, unsigned mask,
        const float* __restrict__ sx, const float* __restrict__ swp,
        const float* __restrict__ sb0, const float* __restrict__ sinv1,
        const float* __restrict__ ssh1, uint32_t* __restrict__ s1bits) {
    int q  = t & 3;
    int r  = t >> 2;          // 0..97
    int xg = r % 7;
    int y  = r / 7;
    int x0 = 2 * xg;

    unsigned long long acc[8];    // acc[2p+j]: ocpair p of quarter, x = x0+j
    #pragma unroll
    for (int i = 0; i < 8; i++) acc[i] = 0ull;

    #pragma unroll
    for (int ky = 0; ky < 3; ky++) {
        #pragma unroll
        for (int kx = 0; kx < 3; kx++) {
            #pragma unroll
            for (int ic = 0; ic < 8; ic++) {
                const float* rr = &sx[(ic * 16 + y + ky) * XPITCH + x0 + kx];
                float a = rr[0];
                float b = rr[1];
                unsigned long long s0 = pack2(a, a);
                unsigned long long s1 = pack2(b, b);
                int k8 = (ky * 3 + kx) * 8 + ic;
                const ulonglong2* wq = (const ulonglong2*)&swp[k8 * 32 + q * 8];
                ulonglong2 wA = wq[0];              // ocpairs 0,1 of quarter
                ulonglong2 wB = wq[1];              // ocpairs 2,3
                acc[0] = fma2(s0, wA.x, acc[0]);
                acc[1] = fma2(s1, wA.x, acc[1]);
                acc[2] = fma2(s0, wA.y, acc[2]);
                acc[3] = fma2(s1, wA.y, acc[3]);
                acc[4] = fma2(s0, wB.x, acc[4]);
                acc[5] = fma2(s1, wB.x, acc[5]);
                acc[6] = fma2(s0, wB.y, acc[6]);
                acc[7] = fma2(s1, wB.y, acc[7]);
            }
        }
    }
    // epilogue: bias + bn1 sign (unfused), 8-bit masks, quad-OR, plain store
    uint32_t m0 = 0u, m1 = 0u;
    #pragma unroll
    for (int p = 0; p < 4; p++) {
        int oc = q * 8 + 2 * p;
        float bL = sb0[oc],   bH = sb0[oc + 1];
        float iL = sinv1[oc], iH = sinv1[oc + 1];
        float sL = ssh1[oc],  sH = ssh1[oc + 1];
        float2 a0 = unpack2(acc[2 * p]);        // x = x0
        float2 a1 = unpack2(acc[2 * p + 1]);    // x = x0+1
        if (__fadd_rn(__fmul_rn(__fadd_rn(a0.x, bL), iL), sL) >= 0.f)
            m0 |= 1u << (2 * p);
        if (__fadd_rn(__fmul_rn(__fadd_rn(a0.y, bH), iH), sH) >= 0.f)
            m0 |= 1u << (2 * p + 1);
        if (__fadd_rn(__fmul_rn(__fadd_rn(a1.x, bL), iL), sL) >= 0.f)
            m1 |= 1u << (2 * p);
        if (__fadd_rn(__fmul_rn(__fadd_rn(a1.y, bH), iH), sH) >= 0.f)
            m1 |= 1u << (2 * p + 1);
    }
    m0 <<= 8 * q;
    m1 <<= 8 * q;
    m0 |= __shfl_xor_sync(mask, m0, 1);
    m0 |= __shfl_xor_sync(mask, m0, 2);
    m1 |= __shfl_xor_sync(mask, m1, 1);
    m1 |= __shfl_xor_sync(mask, m1, 2);
    if (q == 0) {
        s1bits[y * 14 + x0]     = m0;
        s1bits[y * 14 + x0 + 1] = m1;
    }
}

__global__ __launch_bounds__(256, 3) void fused_kernel(
        const float* __restrict__ x,
        const float* __restrict__ b0,
        const float* __restrict__ wlast,
        const float* __restrict__ blast,
        float* __restrict__ out) {
    __shared__ __align__(16) float sx[8 * 16 * XPITCH + 8];
    __shared__ __align__(16) float swp[2304];                // weights [k][oc]
    __shared__ uint32_t s1bits[196];                         // conv0 sign bits
    __shared__ uint32_t sw2b[288];
    __shared__ __align__(16) uint32_t fcb[36];               // 1152 FC input bits
    __shared__ float    h3[516];
    __shared__ float    sb0[32], sinv1[32], ssh1[32];

    const int tid = threadIdx.x;
    const int img = blockIdx.x;

    // ---- Phase A: stage image, weights, constants ---------------------------
    {
        const float4* xin = (const float4*)(x + (size_t)img * 2048);
        for (int i = tid; i < 512; i += 256) {
            float4 v = xin[i];
            int e  = i * 4;
            int ic = e >> 8;
            int rm = e & 255;
            int yy = rm >> 4;
            int xx = rm & 15;
            // xx multiple of 4, row base 80B multiple -> 16B aligned
            *(float4*)&sx[(ic * 16 + yy) * XPITCH + xx] = v;
        }
        for (int i = tid; i < 2304; i += 256) swp[i] = g_w0p[i];
        for (int i = tid; i < 288;  i += 256) sw2b[i] = g_w2bits[i];
        if (tid < 36) fcb[tid] = 0u;
        if (tid < 32) {
            sb0[tid]   = b0[tid];
            sinv1[tid] = g_inv1[tid];
            ssh1[tid]  = g_sh1[tid];
        }
    }
    __syncthreads();

    // ---- Phase B: conv0, 392 tasks (256 + 136) ------------------------------
    conv0_task(tid, 0xffffffffu, sx, swp, sb0, sinv1, ssh1, s1bits);
    if (tid < 136)
        conv0_task(256 + tid, (tid >= 128) ? 0x000000ffu : 0xffffffffu,
                   sx, swp, sb0, sinv1, ssh1, s1bits);
    __syncthreads();

    // ---- Phase C: binary conv2 + maxpool + bn2 sign, sliding reg window ----
    // thread = (c, py): loads 4x14 strip of s1bits once, computes 6 pooled x.
    if (tid < 192) {
        int c  = tid / 6;
        int py = tid % 6;
        int y0 = 2 * py;

        uint32_t wk[9];
        #pragma unroll
        for (int k = 0; k < 9; k++) wk[k] = sw2b[c * 9 + k];

        uint32_t r[4][14];
        #pragma unroll
        for (int dy = 0; dy < 4; dy++)
            #pragma unroll
            for (int xx = 0; xx < 14; xx++)
                r[dy][xx] = s1bits[(y0 + dy) * 14 + xx];

        float inv = g_inv2[c], sh = g_sh2[c];
        uint32_t mask6 = 0u;
        #pragma unroll
        for (int px = 0; px < 6; px++) {
            int maxd = -10000;
            #pragma unroll
            for (int dy = 0; dy < 2; dy++) {
                #pragma unroll
                for (int dx = 0; dx < 2; dx++) {
                    int xx = 2 * px + dx;
                    int p = 0;
                    #pragma unroll
                    for (int ky = 0; ky < 3; ky++) {
                        #pragma unroll
                        for (int kx = 0; kx < 3; kx++)
                            p += __popc(r[dy + ky][xx + kx] ^ wk[ky * 3 + kx]);
                    }
                    int d = 288 - 2 * p;           // exact integer dot
                    maxd = max(maxd, d);
                }
            }
            float v = __fadd_rn(__fmul_rn((float)maxd, inv), sh);
            if (v >= 0.f) mask6 |= 1u << px;
        }
        int base = c * 36 + py * 6;
        int word = base >> 5;
        int off  = base & 31;
        atomicOr(&fcb[word], mask6 << off);
        if (off > 26)
            atomicOr(&fcb[word + 1], mask6 >> (32 - off));
    }
    __syncthreads();

    // ---- Phase D: binary FC (1152 -> 516, exact int) + bn3 + hardtanh ------
    for (int o = tid; o < 516; o += 256) {
        const uint4* wr  = (const uint4*)&g_wfcbits[o * 36];
        const uint4* fb4 = (const uint4*)fcb;
        int p = 0;
        #pragma unroll
        for (int q = 0; q < 9; q++) {
            uint4 wv = wr[q];
            uint4 fv = fb4[q];
            p += __popc(fv.x ^ wv.x) + __popc(fv.y ^ wv.y)
               + __popc(fv.z ^ wv.z) + __popc(fv.w ^ wv.w);
        }
        float d = (float)(1152 - 2 * p);
        float h = __fadd_rn(__fmul_rn(d, g_sc3[o]), g_sh3[o]);  // bn3 UNFUSED
        h3[o] = fminf(1.f, fmaxf(-1.f, h));
    }
    __syncthreads();

    // ---- Phase E: final 516x10 GEMV (fp32) + bias --------------------------
    if (tid < 160) {
        int i = tid >> 4;       // output index 0..9
        int s = tid & 15;       // 16-lane reduction slot
        const float* wr = wlast + i * 516;
        float acc = 0.f;
        for (int j = s; j < 516; j += 16)
            acc = __fmaf_rn(h3[j], wr[j], acc);
        #pragma unroll
        for (int off = 8; off; off >>= 1)
            acc = __fadd_rn(acc, __shfl_xor_sync(0xffffffffu, acc, off, 16));
        if (s == 0)
            out[(size_t)img * 10 + i] = __fadd_rn(acc, blast[i]);
    }
}

extern "C" void kernel_launch(void* const* d_in, const int* in_sizes, int n_in,
                              void* d_out, int out_size) {
    const float* x     = (const float*)d_in[0];
    const float* w0    = (const float*)d_in[1];
    const float* b0    = (const float*)d_in[2];
    const float* g1    = (const float*)d_in[3];
    const float* be1   = (const float*)d_in[4];
    const float* m1    = (const float*)d_in[5];
    const float* v1    = (const float*)d_in[6];
    const float* w2    = (const float*)d_in[7];
    const float* g2    = (const float*)d_in[8];
    const float* be2   = (const float*)d_in[9];
    const float* m2    = (const float*)d_in[10];
    const float* v2    = (const float*)d_in[11];
    const float* wfc   = (const float*)d_in[12];
    const float* g3    = (const float*)d_in[13];
    const float* be3   = (const float*)d_in[14];
    const float* m3    = (const float*)d_in[15];
    const float* v3    = (const float*)d_in[16];
    const float* wlast = (const float*)d_in[17];
    const float* blast = (const float*)d_in[18];
    float* out = (float*)d_out;

    // 288 + 18576 + 32 + 32 + 516 + 2304 = 21748 prep tasks
    prep_kernel<<<85, 256>>>(w0, w2, wfc, g1, be1, m1, v1,
                             g2, be2, m2, v2, g3, be3, m3, v3);
    fused_kernel<<<8192, 256>>>(x, b0, wlast, blast, out);
}

// round 15
// speedup vs baseline: 8.7123x; 8.7123x over previous
#include <cuda_runtime.h>
#include <cstdint>

// ---------------------------------------------------------------------------
// EMGNetQuantized fused BinaryNet inference, XLA-matched fp32 numerics.
// R15: occupancy via geometry, spill-proofed. CTA = 224 threads (= #conv0
// tasks), __launch_bounds__(224,3) -> 96-reg cap, 21 warps/SM. Phase B keeps
// R11's 8oc x 4x tile and bit-exact FMA2 chains ((ky,kx,ic) ascending, acc
// from 0, bias after, unfused bn) but uses alignment-aware per-step loads
// (no 48-reg window) and '#pragma unroll 1' on ky to bound ptxas lookahead
// (the (256,3) spill trap of R13/R14). Phases A/C/D/E restrided to 224.
// ---------------------------------------------------------------------------

__device__ __align__(16) uint32_t g_w2bits[32 * 9];       // [oc][ky*3+kx], bit=ic
__device__ __align__(16) uint32_t g_wfcbits[516 * 36];    // [o][word], bit=col%32
__device__ __align__(16) float    g_w0p[2304];            // [k=(ky3+kx)*8+ic][oc]
__device__ float g_inv1[32], g_sh1[32];                   // bn1 scale/shift
__device__ float g_inv2[32], g_sh2[32];                   // bn2 scale/shift
__device__ float g_sc3[516], g_sh3[516];                  // bn3 scale/shift

__global__ void prep_kernel(const float* __restrict__ w0,
                            const float* __restrict__ w2,
                            const float* __restrict__ wfc,
                            const float* __restrict__ g1, const float* __restrict__ be1,
                            const float* __restrict__ m1, const float* __restrict__ v1,
                            const float* __restrict__ g2, const float* __restrict__ be2,
                            const float* __restrict__ m2, const float* __restrict__ v2,
                            const float* __restrict__ g3, const float* __restrict__ be3,
                            const float* __restrict__ m3, const float* __restrict__ v3) {
    int t = blockIdx.x * blockDim.x + threadIdx.x;
    if (t < 288) {
        int oc = t / 9, k = t % 9;
        uint32_t w = 0u;
        #pragma unroll 4
        for (int ic = 0; ic < 32; ic++)
            if (w2[oc * 288 + ic * 9 + k] >= 0.f) w |= (1u << ic);
        g_w2bits[t] = w;
    } else if (t < 288 + 18576) {
        int j = t - 288;
        int o = j / 36, c = j % 36;
        const float* row = wfc + o * 1152 + c * 32;
        uint32_t w = 0u;
        #pragma unroll 4
        for (int b = 0; b < 32; b++)
            if (row[b] >= 0.f) w |= (1u << b);
        g_wfcbits[j] = w;
    } else if (t < 288 + 18576 + 32) {
        int c = t - (288 + 18576);
        float inv = __fdiv_rn(g1[c], __fsqrt_rn(__fadd_rn(v1[c], 1e-5f)));
        g_inv1[c] = inv;
        g_sh1[c]  = __fsub_rn(be1[c], __fmul_rn(m1[c], inv));
    } else if (t < 288 + 18576 + 64) {
        int c = t - (288 + 18576 + 32);
        float inv = __fdiv_rn(g2[c], __fsqrt_rn(__fadd_rn(v2[c], 1e-5f)));
        g_inv2[c] = inv;
        g_sh2[c]  = __fsub_rn(be2[c], __fmul_rn(m2[c], inv));
    } else if (t < 288 + 18576 + 64 + 516) {
        int c = t - (288 + 18576 + 64);
        float inv = __fdiv_rn(g3[c], __fsqrt_rn(__fadd_rn(v3[c], 1e-5f)));
        g_sc3[c] = inv;
        g_sh3[c] = __fsub_rn(be3[c], __fmul_rn(m3[c], inv));
    } else if (t < 288 + 18576 + 64 + 516 + 2304) {
        // transpose w0 -> [k][oc] so per-CTA loads are linear/coalesced
        int j  = t - (288 + 18576 + 64 + 516);
        int oc = j & 31;
        int r  = j >> 5;
        int ic = r & 7;
        int kk = r >> 3;                  // ky*3+kx
        g_w0p[j] = w0[oc * 72 + ic * 9 + kk];
    }
}

// ---- f32x2 helpers (per-lane IEEE RN fma; bit-identical to scalar) ---------
__device__ __forceinline__ unsigned long long fma2(unsigned long long a,
                                                   unsigned long long b,
                                                   unsigned long long c) {
    unsigned long long d;
    asm("fma.rn.f32x2 %0, %1, %2, %3;" : "=l"(d) : "l"(a), "l"(b), "l"(c));
    return d;
}
__device__ __forceinline__ unsigned long long pack2(float lo, float hi) {
    unsigned long long r;
    asm("mov.b64 %0, {%1, %2};" : "=l"(r) : "f"(lo), "f"(hi));
    return r;
}
__device__ __forceinline__ float2 unpack2(unsigned long long v) {
    float lo, hi;
    asm("mov.b64 {%0, %1}, %2;" : "=f"(lo), "=f"(hi) : "l"(v));
    return make_float2(lo, hi);
}

#define XPITCH 20   // sx row pitch in floats: 80B rows -> 16B-aligned
#define NT 224      // threads per CTA

__global__ __launch_bounds__(NT, 3) void fused_kernel(
        const float* __restrict__ x,
        const float* __restrict__ b0,
        const float* __restrict__ wlast,
        const float* __restrict__ blast,
        float* __restrict__ out) {
    __shared__ __align__(16) float sx[8 * 16 * XPITCH + 8];
    __shared__ __align__(16) float swp[2304];                // weights [k][oc]
    __shared__ uint32_t s1bits[196];                         // conv0 sign bits
    __shared__ uint32_t sw2b[288];
    __shared__ __align__(16) uint32_t fcb[36];               // 1152 FC input bits
    __shared__ float    h3[516];
    __shared__ float    sb0[32], sinv1[32], ssh1[32];

    const int tid = threadIdx.x;
    const int img = blockIdx.x;

    // ---- Phase A: stage image, weights (vectorized), constants -------------
    {
        const float4* xin = (const float4*)(x + (size_t)img * 2048);
        for (int i = tid; i < 512; i += NT) {
            float4 v = xin[i];
            int e  = i * 4;
            int ic = e >> 8;
            int rm = e & 255;
            int yy = rm >> 4;
            int xx = rm & 15;
            // xx multiple of 4, row base 80B multiple -> 16B aligned
            *(float4*)&sx[(ic * 16 + yy) * XPITCH + xx] = v;
        }
        const float4* wp4 = (const float4*)g_w0p;
        for (int i = tid; i < 576; i += NT) ((float4*)swp)[i] = wp4[i];
        for (int i = tid; i < 288; i += NT) sw2b[i] = g_w2bits[i];
        for (int i = tid; i < 196; i += NT) s1bits[i] = 0u;
        if (tid < 36) fcb[tid] = 0u;
        if (tid < 32) {
            sb0[tid]   = b0[tid];
            sinv1[tid] = g_inv1[tid];
            ssh1[tid]  = g_sh1[tid];
        }
    }
    __syncthreads();

    // ---- Phase B: conv0, 8oc x 4x tile, one task per thread ----------------
    // task = tid: y = tid%14, t2 = tid/14, xgg = t2&3, q = t2>>2.
    // FMA chain per acc: (ky,kx,ic) ascending, acc from 0 — bit-exact R11.
    {
        int y   = tid % 14;
        int t2  = tid / 14;          // 0..15
        int xgg = t2 & 3;
        int q   = t2 >> 2;           // 0..3
        int x0  = 4 * xgg;
        int nx  = (xgg == 3) ? 2 : 4;

        unsigned long long acc[16];  // acc[p*4+j], p=ocpair in quarter, j=x
        #pragma unroll
        for (int i = 0; i < 16; i++) acc[i] = 0ull;

        #pragma unroll 1             // bound ptxas lookahead: anti-spill
        for (int ky = 0; ky < 3; ky++) {
            #pragma unroll
            for (int kx = 0; kx < 3; kx++) {
                #pragma unroll
                for (int ic = 0; ic < 8; ic++) {
                    const float* base = &sx[(ic * 16 + y + ky) * XPITCH + x0];
                    float f0, f1, f2, f3;
                    if (kx == 0) {           // aligned float4
                        float4 v = *(const float4*)base;
                        f0 = v.x; f1 = v.y; f2 = v.z; f3 = v.w;
                    } else if (kx == 1) {    // [1] + {2,3} + [4]
                        f0 = base[1];
                        float2 m = *(const float2*)(base + 2);
                        f1 = m.x; f2 = m.y;
                        f3 = base[4];
                    } else {                 // {2,3} + {4,5}
                        float2 a2 = *(const float2*)(base + 2);
                        float2 b2 = *(const float2*)(base + 4);
                        f0 = a2.x; f1 = a2.y; f2 = b2.x; f3 = b2.y;
                    }
                    unsigned long long s0 = pack2(f0, f0);
                    unsigned long long s1 = pack2(f1, f1);
                    unsigned long long s2 = pack2(f2, f2);
                    unsigned long long s3 = pack2(f3, f3);
                    int k8 = (ky * 3 + kx) * 8 + ic;
                    const ulonglong2* wq =
                        (const ulonglong2*)&swp[k8 * 32 + q * 8];
                    ulonglong2 wA = wq[0];     // oc pairs 0,1 of quarter
                    ulonglong2 wB = wq[1];     // oc pairs 2,3
                    acc[0]  = fma2(s0, wA.x, acc[0]);
                    acc[1]  = fma2(s1, wA.x, acc[1]);
                    acc[2]  = fma2(s2, wA.x, acc[2]);
                    acc[3]  = fma2(s3, wA.x, acc[3]);
                    acc[4]  = fma2(s0, wA.y, acc[4]);
                    acc[5]  = fma2(s1, wA.y, acc[5]);
                    acc[6]  = fma2(s2, wA.y, acc[6]);
                    acc[7]  = fma2(s3, wA.y, acc[7]);
                    acc[8]  = fma2(s0, wB.x, acc[8]);
                    acc[9]  = fma2(s1, wB.x, acc[9]);
                    acc[10] = fma2(s2, wB.x, acc[10]);
                    acc[11] = fma2(s3, wB.x, acc[11]);
                    acc[12] = fma2(s0, wB.y, acc[12]);
                    acc[13] = fma2(s1, wB.y, acc[13]);
                    acc[14] = fma2(s2, wB.y, acc[14]);
                    acc[15] = fma2(s3, wB.y, acc[15]);
                }
            }
        }
        // epilogue: bias + bn1 sign (unfused), 8-bit masks per x, one OR each
        uint32_t mj[4] = {0u, 0u, 0u, 0u};
        #pragma unroll
        for (int p = 0; p < 4; p++) {
            int ocL = q * 8 + 2 * p;
            float biasL = sb0[ocL],     biasH = sb0[ocL + 1];
            float invL  = sinv1[ocL],   invH  = sinv1[ocL + 1];
            float shL   = ssh1[ocL],    shH   = ssh1[ocL + 1];
            #pragma unroll
            for (int j = 0; j < 4; j++) {
                float2 a = unpack2(acc[p * 4 + j]);
                if (__fadd_rn(__fmul_rn(__fadd_rn(a.x, biasL), invL), shL) >= 0.f)
                    mj[j] |= 1u << (2 * p);
                if (__fadd_rn(__fmul_rn(__fadd_rn(a.y, biasH), invH), shH) >= 0.f)
                    mj[j] |= 1u << (2 * p + 1);
            }
        }
        #pragma unroll
        for (int j = 0; j < 4; j++)
            if (j < nx)
                atomicOr(&s1bits[y * 14 + x0 + j], mj[j] << (8 * q));
    }
    __syncthreads();

    // ---- Phase C: binary conv2 + maxpool + bn2 sign, sliding reg window ----
    // thread = (c, py): loads 4x14 strip of s1bits once, computes 6 pooled x.
    if (tid < 192) {
        int c  = tid / 6;
        int py = tid % 6;
        int y0 = 2 * py;

        uint32_t wk[9];
        #pragma unroll
        for (int k = 0; k < 9; k++) wk[k] = sw2b[c * 9 + k];

        uint32_t r[4][14];
        #pragma unroll
        for (int dy = 0; dy < 4; dy++)
            #pragma unroll
            for (int xx = 0; xx < 14; xx++)
                r[dy][xx] = s1bits[(y0 + dy) * 14 + xx];

        float inv = g_inv2[c], sh = g_sh2[c];
        uint32_t mask6 = 0u;
        #pragma unroll
        for (int px = 0; px < 6; px++) {
            int maxd = -10000;
            #pragma unroll
            for (int dy = 0; dy < 2; dy++) {
                #pragma unroll
                for (int dx = 0; dx < 2; dx++) {
                    int xx = 2 * px + dx;
                    int p = 0;
                    #pragma unroll
                    for (int ky = 0; ky < 3; ky++) {
                        #pragma unroll
                        for (int kx = 0; kx < 3; kx++)
                            p += __popc(r[dy + ky][xx + kx] ^ wk[ky * 3 + kx]);
                    }
                    int d = 288 - 2 * p;           // exact integer dot
                    maxd = max(maxd, d);
                }
            }
            float v = __fadd_rn(__fmul_rn((float)maxd, inv), sh);
            if (v >= 0.f) mask6 |= 1u << px;
        }
        int base = c * 36 + py * 6;
        int word = base >> 5;
        int off  = base & 31;
        atomicOr(&fcb[word], mask6 << off);
        if (off > 26)
            atomicOr(&fcb[word + 1], mask6 >> (32 - off));
    }
    __syncthreads();

    // ---- Phase D: binary FC (1152 -> 516, exact int) + bn3 + hardtanh ------
    for (int o = tid; o < 516; o += NT) {
        const uint4* wr  = (const uint4*)&g_wfcbits[o * 36];
        const uint4* fb4 = (const uint4*)fcb;
        int p = 0;
        #pragma unroll
        for (int q = 0; q < 9; q++) {
            uint4 wv = wr[q];
            uint4 fv = fb4[q];
            p += __popc(fv.x ^ wv.x) + __popc(fv.y ^ wv.y)
               + __popc(fv.z ^ wv.z) + __popc(fv.w ^ wv.w);
        }
        float d = (float)(1152 - 2 * p);
        float h = __fadd_rn(__fmul_rn(d, g_sc3[o]), g_sh3[o]);  // bn3 UNFUSED
        h3[o] = fminf(1.f, fmaxf(-1.f, h));
    }
    __syncthreads();

    // ---- Phase E: final 516x10 GEMV (fp32) + bias --------------------------
    if (tid < 160) {
        int i = tid >> 4;       // output index 0..9
        int s = tid & 15;       // 16-lane reduction slot
        const float* wr = wlast + i * 516;
        float acc = 0.f;
        for (int j = s; j < 516; j += 16)
            acc = __fmaf_rn(h3[j], wr[j], acc);
        #pragma unroll
        for (int off = 8; off; off >>= 1)
            acc = __fadd_rn(acc, __shfl_xor_sync(0xffffffffu, acc, off, 16));
        if (s == 0)
            out[(size_t)img * 10 + i] = __fadd_rn(acc, blast[i]);
    }
}

extern "C" void kernel_launch(void* const* d_in, const int* in_sizes, int n_in,
                              void* d_out, int out_size) {
    const float* x     = (const float*)d_in[0];
    const float* w0    = (const float*)d_in[1];
    const float* b0    = (const float*)d_in[2];
    const float* g1    = (const float*)d_in[3];
    const float* be1   = (const float*)d_in[4];
    const float* m1    = (const float*)d_in[5];
    const float* v1    = (const float*)d_in[6];
    const float* w2    = (const float*)d_in[7];
    const float* g2    = (const float*)d_in[8];
    const float* be2   = (const float*)d_in[9];
    const float* m2    = (const float*)d_in[10];
    const float* v2    = (const float*)d_in[11];
    const float* wfc   = (const float*)d_in[12];
    const float* g3    = (const float*)d_in[13];
    const float* be3   = (const float*)d_in[14];
    const float* m3    = (const float*)d_in[15];
    const float* v3    = (const float*)d_in[16];
    const float* wlast = (const float*)d_in[17];
    const float* blast = (const float*)d_in[18];
    float* out = (float*)d_out;

    // 288 + 18576 + 32 + 32 + 516 + 2304 = 21748 prep tasks
    prep_kernel<<<85, 256>>>(w0, w2, wfc, g1, be1, m1, v1,
                             g2, be2, m2, v2, g3, be3, m3, v3);
    fused_kernel<<<8192, NT>>>(x, b0, wlast, blast, out);
}